// round 9
// baseline (speedup 1.0000x reference)
#include <cuda_runtime.h>

// SPADE: InstanceNorm2d(affine=False) + per-pixel class-conditional affine.
// x[8,128,256,256] f32, segmap[8,20,256,256] f32, weight/bias[20,128] f32.
//
// R9: launch-chained image PAIRS (L2 reuse across launch boundaries; L2
// persists across launches, only L1 is flushed):
//   argmax (once)
//   for p in 0..3:  stats(pair p)  grid 2048  (fills L2 with x_pair, 67 MB)
//                   apply(pair p)  grid 2048  (x reads hit L2, writes stream)
// No grid barriers, no tickets: every hot loop is an uninterrupted batched
// load stream (this is what hit the ~6.5 TB/s LTS cap in R2).

#define N_   8
#define C_   128
#define H_   256
#define W_   256
#define L_   20
#define HW_  (H_ * W_)      // 65536
#define EPS_ 1e-5f

#define CGRP 8              // channels per apply block
#define WBS  9              // padded (w,b) row stride: l*9 mod 32 distinct for l<20

// Eighth-plane partials (sum, sumsq), indexed by image parity (pair-local).
__device__ float2 g_part[2][C_][8];
// Per-pixel argmax class id.
__device__ unsigned char g_cls[N_ * HW_];   // 512 KB

// ---------------------------------------------------------------------------
// Argmax: thread = 4 adjacent pixels (float4 per plane). Grid 512.
// Streaming reads (segmap is read once). cls map cached (re-read 8x).
// ---------------------------------------------------------------------------
__global__ void __launch_bounds__(256) spade_argmax_kernel(const float* __restrict__ seg) {
    const int idx = blockIdx.x * 256 + threadIdx.x;     // over N*HW/4
    const int n   = idx >> 14;
    const int p4  = idx & 16383;
    const float4* __restrict__ s =
        reinterpret_cast<const float4*>(seg + (size_t)n * L_ * HW_) + p4;

    float4 best = __ldcs(s);
    int b0 = 0, b1 = 0, b2 = 0, b3 = 0;
    #pragma unroll
    for (int l = 1; l < L_; l++) {
        float4 v = __ldcs(s + (size_t)l * (HW_ / 4));
        if (v.x > best.x) { best.x = v.x; b0 = l; }
        if (v.y > best.y) { best.y = v.y; b1 = l; }
        if (v.z > best.z) { best.z = v.z; b2 = l; }
        if (v.w > best.w) { best.w = v.w; b3 = l; }
    }
    *reinterpret_cast<uchar4*>(g_cls + (size_t)n * HW_ + p4 * 4) =
        make_uchar4((unsigned char)b0, (unsigned char)b1,
                    (unsigned char)b2, (unsigned char)b3);
}

// ---------------------------------------------------------------------------
// Stats for image pair (n0, n0+1). Grid 2048: block -> (img, plane, eighth).
// One uninterrupted 8-deep batched load loop (8192 floats per block).
// Cached loads fill L2 for the apply launch that follows.
// ---------------------------------------------------------------------------
__global__ void __launch_bounds__(256) spade_stats_kernel(const float* __restrict__ x, int n0) {
    const int b = blockIdx.x;                 // 0..2047
    const int n = n0 + (b >> 10);
    const int c = (b >> 3) & 127;
    const int e = b & 7;
    const float4* __restrict__ p =
        reinterpret_cast<const float4*>(x + (size_t)(n * C_ + c) * HW_) + e * 2048;

    float sm = 0.f, s2 = 0.f;
    {
        float4 v[8];
        #pragma unroll
        for (int i = 0; i < 8; i++)            // 8 * 256 = 2048 float4
            v[i] = __ldg(p + i * 256 + threadIdx.x);
        #pragma unroll
        for (int i = 0; i < 8; i++) {
            sm += (v[i].x + v[i].y) + (v[i].z + v[i].w);
            s2 += v[i].x * v[i].x + v[i].y * v[i].y
                + v[i].z * v[i].z + v[i].w * v[i].w;
        }
    }
    #pragma unroll
    for (int o = 16; o > 0; o >>= 1) {
        sm += __shfl_down_sync(0xFFFFFFFFu, sm, o);
        s2 += __shfl_down_sync(0xFFFFFFFFu, s2, o);
    }
    __shared__ float ss[8], ss2[8];
    const int wid = threadIdx.x >> 5, lid = threadIdx.x & 31;
    if (lid == 0) { ss[wid] = sm; ss2[wid] = s2; }
    __syncthreads();
    if (threadIdx.x == 0) {
        float ts = 0.f, ts2 = 0.f;
        #pragma unroll
        for (int i = 0; i < 8; i++) { ts += ss[i]; ts2 += ss2[i]; }
        g_part[n & 1][c][e] = make_float2(ts, ts2);
    }
}

// ---------------------------------------------------------------------------
// Apply for image pair (n0, n0+1). Grid 2048:
//   block -> img = n0 + (b>>10); r = b&1023: cgroup = r&15 (8 ch),
//   slab = r>>4 (4 rows). Thread = float4 of pixels.
// x reads: __ldcs (hit L2 from stats, evict after use).
// out writes: __stcs (streaming, don't pollute L2).
// Per-block (w,b) sub-table: 20 x 8 float2, stride 9 -> conflict-free LDS.
// ---------------------------------------------------------------------------
__global__ void __launch_bounds__(256) spade_apply_kernel(
    const float* __restrict__ x,
    const float* __restrict__ wgt,
    const float* __restrict__ bia,
    float* __restrict__ out,
    int n0)
{
    __shared__ float2 s_wb[L_ * WBS];
    __shared__ float2 s_ms[CGRP];

    const int b    = blockIdx.x;              // 0..2047
    const int n    = n0 + (b >> 10);
    const int r_   = b & 1023;
    const int c0   = (r_ & 15) * CGRP;
    const int h0   = (r_ >> 4) << 2;
    const int tid  = threadIdx.x;

    // Stage this cgroup's (w,b) rows and finalize its stats.
    if (tid < L_ * CGRP) {
        const int l = tid >> 3, c = tid & 7;
        s_wb[l * WBS + c] =
            make_float2(__ldg(wgt + l * C_ + c0 + c), __ldg(bia + l * C_ + c0 + c));
    }
    if (tid >= 224 && tid < 224 + CGRP) {     // separate warp from stagers
        const int c = tid - 224;
        const float2* pp = g_part[n & 1][c0 + c];
        float ts = 0.f, ts2 = 0.f;
        #pragma unroll
        for (int i = 0; i < 8; i++) { ts += pp[i].x; ts2 += pp[i].y; }
        const float inv_hw = 1.0f / (float)HW_;
        float mean = ts * inv_hw;
        float var  = ts2 * inv_hw - mean * mean;
        if (var < 0.f) var = 0.f;
        s_ms[c] = make_float2(mean, rsqrtf(var + EPS_));
    }

    const int rr   = tid >> 6;
    const int col4 = (tid & 63) << 2;
    const int pix  = (h0 + rr) * W_ + col4;

    const uchar4 cl = *reinterpret_cast<const uchar4*>(g_cls + (size_t)n * HW_ + pix);
    const int i0 = cl.x * WBS, i1 = cl.y * WBS, i2 = cl.z * WBS, i3 = cl.w * WBS;
    __syncthreads();

    const float* __restrict__ xn = x   + (size_t)(n * C_ + c0) * HW_ + pix;
    float*       __restrict__ on = out + (size_t)(n * C_ + c0) * HW_ + pix;

    float4 v[CGRP];
    #pragma unroll
    for (int c = 0; c < CGRP; c++)             // 8 outstanding 16B loads
        v[c] = __ldcs(reinterpret_cast<const float4*>(xn + (size_t)c * HW_));
    #pragma unroll
    for (int c = 0; c < CGRP; c++) {
        const float2 ms = s_ms[c];
        const float2 w0 = s_wb[i0 + c];
        const float2 w1 = s_wb[i1 + c];
        const float2 w2 = s_wb[i2 + c];
        const float2 w3 = s_wb[i3 + c];
        float4 o;
        o.x = fmaf((v[c].x - ms.x) * ms.y, w0.x, w0.y);
        o.y = fmaf((v[c].y - ms.x) * ms.y, w1.x, w1.y);
        o.z = fmaf((v[c].z - ms.x) * ms.y, w2.x, w2.y);
        o.w = fmaf((v[c].w - ms.x) * ms.y, w3.x, w3.y);
        __stcs(reinterpret_cast<float4*>(on + (size_t)c * HW_), o);
    }
}

// ---------------------------------------------------------------------------
extern "C" void kernel_launch(void* const* d_in, const int* in_sizes, int n_in,
                              void* d_out, int out_size) {
    const float* x   = (const float*)d_in[0];
    const float* seg = (const float*)d_in[1];
    const float* wgt = (const float*)d_in[2];
    const float* bia = (const float*)d_in[3];
    float* out = (float*)d_out;

    spade_argmax_kernel<<<512, 256>>>(seg);
    for (int p = 0; p < 4; p++) {
        spade_stats_kernel<<<2048, 256>>>(x, 2 * p);
        spade_apply_kernel<<<2048, 256>>>(x, wgt, bia, out, 2 * p);
    }
}

// round 10
// speedup vs baseline: 1.1899x; 1.1899x over previous
#include <cuda_runtime.h>

// SPADE: InstanceNorm2d(affine=False) + per-pixel class-conditional affine.
// x[8,128,256,256] f32, segmap[8,20,256,256] f32, weight/bias[20,128] f32.
//
// R10 = R5 skeleton (best: role-split persistent, L2 chaining) with a
// register-cached-(w,b) apply item: thread = 2 pixels x 8 channels, class
// lookups hoisted out of the channel loop (LDS traffic cut 4x: 32B -> 8B
// per pixel-channel). Phases:
//   phase 0:   [176 blocks] stats(img 0)  || [336 blocks] argmax
//   phase k:   [176 blocks] stats(img k)  || [336 blocks] apply(img k-1)
//   tail:      [336 blocks] apply(img 7)

#define N_   8
#define C_   128
#define H_   256
#define W_   256
#define L_   20
#define HW_  (H_ * W_)      // 65536
#define EPS_ 1e-5f

#define GRID    512
#define THREADS 256
#define SB      176          // stats blocks
#define AB      (GRID - SB)  // 336 apply blocks
#define CGRP    8            // channels per apply item
#define AITEMS  2048         // (HW/512 pixel slabs=128) * 16 cgroups
#define WB_STRIDE 129        // full-table padded stride

// Quarter-plane partials (sum, sumsq), double-buffered by image parity.
__device__ float2 g_part[2][C_ * 4];
// Per-pixel argmax class id.
__device__ unsigned char g_cls[N_ * HW_];   // 512 KB
// Grid barrier: g_gen monotonic across launches/replays.
__device__ unsigned int g_count = 0;
__device__ unsigned int g_gen   = 0;

// ---------------------------------------------------------------------------
__device__ __forceinline__ void grid_barrier() {
    __syncthreads();
    if (threadIdx.x == 0) {
        unsigned int snap = *(volatile unsigned int*)&g_gen;
        __threadfence();
        unsigned int t = atomicAdd(&g_count, 1u);
        if (t == GRID - 1) {
            atomicExch(&g_count, 0u);
            __threadfence();
            atomicAdd(&g_gen, 1u);
        } else {
            while (*(volatile unsigned int*)&g_gen == snap) { __nanosleep(64); }
        }
        __threadfence();
    }
    __syncthreads();
}

// ---------------------------------------------------------------------------
// Stats item s in [0,512): plane c = s>>2, quarter q = s&3 (16384 floats).
// Normal cached loads -> x_n resident in L2 for next phase's apply.
// ---------------------------------------------------------------------------
__device__ __forceinline__ void do_stats_item(const float* __restrict__ x, int n, int s) {
    const int c = s >> 2;
    const int q = s & 3;
    const float4* __restrict__ p =
        reinterpret_cast<const float4*>(x + (size_t)(n * C_ + c) * HW_) + q * 4096;

    float sm = 0.f, s2 = 0.f;
    #pragma unroll
    for (int i = 0; i < 16; i++) {             // 16 * 256 = 4096 float4
        float4 v = __ldg(p + i * 256 + threadIdx.x);
        sm += (v.x + v.y) + (v.z + v.w);
        s2 += v.x * v.x + v.y * v.y + v.z * v.z + v.w * v.w;
    }
    #pragma unroll
    for (int o = 16; o > 0; o >>= 1) {
        sm += __shfl_down_sync(0xFFFFFFFFu, sm, o);
        s2 += __shfl_down_sync(0xFFFFFFFFu, s2, o);
    }
    __shared__ float ss[8], ss2[8];
    const int wid = threadIdx.x >> 5, lid = threadIdx.x & 31;
    if (lid == 0) { ss[wid] = sm; ss2[wid] = s2; }
    __syncthreads();
    if (threadIdx.x == 0) {
        float ts = 0.f, ts2 = 0.f;
        #pragma unroll
        for (int i = 0; i < 8; i++) { ts += ss[i]; ts2 += ss2[i]; }
        g_part[n & 1][c * 4 + q] = make_float2(ts, ts2);
    }
    __syncthreads();
}

// ---------------------------------------------------------------------------
// Argmax item i in [0,512): 1024 consecutive pixels (thread = float4).
// ---------------------------------------------------------------------------
__device__ __forceinline__ void do_argmax_item(const float* __restrict__ seg, int i) {
    const int idx = i * THREADS + threadIdx.x;           // 0 .. 131071
    const int n   = idx >> 14;
    const int p4  = idx & 16383;
    const float4* __restrict__ s =
        reinterpret_cast<const float4*>(seg + (size_t)n * L_ * HW_) + p4;

    float4 best = __ldcs(s);
    int b0 = 0, b1 = 0, b2 = 0, b3 = 0;
    #pragma unroll
    for (int l = 1; l < L_; l++) {
        float4 v = __ldcs(s + (size_t)l * (HW_ / 4));
        if (v.x > best.x) { best.x = v.x; b0 = l; }
        if (v.y > best.y) { best.y = v.y; b1 = l; }
        if (v.z > best.z) { best.z = v.z; b2 = l; }
        if (v.w > best.w) { best.w = v.w; b3 = l; }
    }
    *reinterpret_cast<uchar4*>(g_cls + (size_t)n * HW_ + p4 * 4) =
        make_uchar4((unsigned char)b0, (unsigned char)b1,
                    (unsigned char)b2, (unsigned char)b3);
}

// ---------------------------------------------------------------------------
// Apply item a in [0,2048): cgroup = a&15 (8 channels), 2-row slab = a>>4.
// Thread = 2 adjacent pixels (float2). Class-conditional (w,b) for both
// pixels is hoisted into 32 registers BEFORE the channel loop -> the inner
// loop does no table LDS at all (only broadcast ms reads).
// x reads: __ldcs (L2 hit from stats phase). out: __stcs streaming.
// ---------------------------------------------------------------------------
__device__ __forceinline__ void do_apply_item(
    const float* __restrict__ x, float* __restrict__ out,
    const float2* __restrict__ s_wb, const float2* __restrict__ s_ms,
    int n, int a)
{
    const int c0  = (a & 15) * CGRP;
    const int h0  = (a >> 4) << 1;            // 2-row slab
    const int tid = threadIdx.x;

    const int r    = tid >> 7;                // 0..1
    const int col2 = (tid & 127) << 1;        // 0..254
    const int pix  = (h0 + r) * W_ + col2;

    // Two classes for this thread's two pixels.
    const unsigned char* cp = g_cls + (size_t)n * HW_ + pix;
    const int clA = cp[0], clB = cp[1];

    // Hoist (w,b) for both classes, 8 channels -> 32 registers.
    float2 wbA[CGRP], wbB[CGRP];
    {
        const float2* rowA = s_wb + clA * WB_STRIDE + c0;
        const float2* rowB = s_wb + clB * WB_STRIDE + c0;
        #pragma unroll
        for (int i = 0; i < CGRP; i++) { wbA[i] = rowA[i]; wbB[i] = rowB[i]; }
    }

    const float* __restrict__ xn = x   + (size_t)(n * C_ + c0) * HW_ + pix;
    float*       __restrict__ on = out + (size_t)(n * C_ + c0) * HW_ + pix;

    // Batch all 8 channel loads for MLP, then compute + stream stores.
    float2 v[CGRP];
    #pragma unroll
    for (int c = 0; c < CGRP; c++)
        v[c] = __ldcs(reinterpret_cast<const float2*>(xn + (size_t)c * HW_));
    #pragma unroll
    for (int c = 0; c < CGRP; c++) {
        const float2 ms = s_ms[c0 + c];       // uniform -> LDS broadcast
        float2 o;
        o.x = fmaf((v[c].x - ms.x) * ms.y, wbA[c].x, wbA[c].y);
        o.y = fmaf((v[c].y - ms.x) * ms.y, wbB[c].x, wbB[c].y);
        __stcs(reinterpret_cast<float2*>(on + (size_t)c * HW_), o);
    }
}

// ---------------------------------------------------------------------------
__device__ __forceinline__ void finalize_stats(float2* s_ms, int n) {
    if (threadIdx.x < C_) {
        const float2* pp = &g_part[n & 1][threadIdx.x * 4];
        float ts  = (pp[0].x + pp[1].x) + (pp[2].x + pp[3].x);
        float ts2 = (pp[0].y + pp[1].y) + (pp[2].y + pp[3].y);
        const float inv_hw = 1.0f / (float)HW_;
        float mean = ts * inv_hw;
        float var  = ts2 * inv_hw - mean * mean;
        if (var < 0.f) var = 0.f;
        s_ms[threadIdx.x] = make_float2(mean, rsqrtf(var + EPS_));
    }
    __syncthreads();
}

// ---------------------------------------------------------------------------
__global__ void __launch_bounds__(THREADS, 4) spade_fused_kernel(
    const float* __restrict__ x,
    const float* __restrict__ seg,
    const float* __restrict__ wgt,
    const float* __restrict__ bia,
    float* __restrict__ out)
{
    __shared__ float2 s_wb[L_ * WB_STRIDE];   // full merged (w,b) table
    __shared__ float2 s_ms[C_];               // per-channel (mean, invstd)

    const int b = blockIdx.x;
    const bool is_stats = (b < SB);
    const int b2 = b - SB;

    // Stage the full (w,b) table once.
    for (int i = threadIdx.x; i < L_ * C_; i += THREADS) {
        int l = i >> 7, c = i & (C_ - 1);
        s_wb[l * WB_STRIDE + c] = make_float2(__ldg(wgt + i), __ldg(bia + i));
    }

    // Phase 0: stats(0) || argmax
    if (is_stats) {
        for (int s = b; s < 512; s += SB) do_stats_item(x, 0, s);
    } else {
        for (int i = b2; i < 512; i += AB) do_argmax_item(seg, i);
    }
    grid_barrier();

    // Phases 1..7: stats(k) || apply(k-1)
    for (int k = 1; k < N_; k++) {
        if (is_stats) {
            for (int s = b; s < 512; s += SB) do_stats_item(x, k, s);
        } else {
            finalize_stats(s_ms, k - 1);
            for (int a = b2; a < AITEMS; a += AB)
                do_apply_item(x, out, s_wb, s_ms, k - 1, a);
        }
        grid_barrier();
    }

    // Tail: apply(7)
    if (!is_stats) {
        finalize_stats(s_ms, N_ - 1);
        for (int a = b2; a < AITEMS; a += AB)
            do_apply_item(x, out, s_wb, s_ms, N_ - 1, a);
    }
}

// ---------------------------------------------------------------------------
extern "C" void kernel_launch(void* const* d_in, const int* in_sizes, int n_in,
                              void* d_out, int out_size) {
    const float* x   = (const float*)d_in[0];
    const float* seg = (const float*)d_in[1];
    const float* wgt = (const float*)d_in[2];
    const float* bia = (const float*)d_in[3];
    float* out = (float*)d_out;

    spade_fused_kernel<<<GRID, THREADS>>>(x, seg, wgt, bia, out);
}

// round 11
// speedup vs baseline: 1.2090x; 1.0161x over previous
#include <cuda_runtime.h>

// SPADE: InstanceNorm2d(affine=False) + per-pixel class-conditional affine.
// x[8,128,256,256] f32, segmap[8,20,256,256] f32, weight/bias[20,128] f32.
//
// R11: persistent kernel, BARRIER-FREE pipelined ticket queue.
// Queue order: [argmax/stats(0) | stats(k)+apply(k-1) regions | apply(7)].
// Apply(k) items gate on g_ready[k] (set by the finisher stats block, which
// also precomputes all 128 per-channel (mean, invstd) into g_ms[k]) and on
// g_argdone==512. Producers precede consumers in ticket order -> gates are
// nearly-always open, DRAM streams never drain. One terminal barrier resets
// all counters (replay-safe; g_gen monotonic).

#define N_   8
#define C_   128
#define H_   256
#define W_   256
#define L_   20
#define HW_  (H_ * W_)      // 65536
#define EPS_ 1e-5f

#define GRID    512
#define THREADS 256
#define CGRP    8            // channels per apply item (16 cgroups)
#define WB_STRIDE 129        // padded stride for full (w,b) table

// Region layout in ticket space
#define REG0_END   1024u                      // 512 argmax + 512 stats(0)
#define REGK_SIZE  1536u                      // 512 stats(k) + 1024 apply(k-1)
#define REG8_BEGIN (REG0_END + 7u * REGK_SIZE)   // 11776
#define TOTAL_TKTS (REG8_BEGIN + 1024u)          // 12800

// Quarter-plane partials (sum, sumsq) per image.
__device__ float2 g_part[N_][C_ * 4];
// Finalized per-channel (mean, invstd) per image (by finisher block).
__device__ float2 g_ms[N_][C_];
// Per-pixel argmax class id.
__device__ unsigned char g_cls[N_ * HW_];   // 512 KB
// Pipeline state (all reset by terminal barrier -> graph-replay safe).
__device__ unsigned int g_ticket  = 0;
__device__ unsigned int g_done[N_] = {0,0,0,0,0,0,0,0};
__device__ unsigned int g_ready[N_] = {0,0,0,0,0,0,0,0};
__device__ unsigned int g_argdone = 0;
__device__ unsigned int g_count   = 0;
__device__ unsigned int g_gen     = 0;      // monotonic across replays

// ---------------------------------------------------------------------------
// Stats item s in [0,512): plane c = s>>2, quarter q = s&3 (16384 floats).
// Cached loads -> x_n resident in L2 for the apply items that follow.
// The block completing the 512th item finalizes g_ms[n] and sets g_ready[n].
// ---------------------------------------------------------------------------
__device__ __forceinline__ void do_stats_item(const float* __restrict__ x, int n, int s) {
    const int c = s >> 2;
    const int q = s & 3;
    const float4* __restrict__ p =
        reinterpret_cast<const float4*>(x + (size_t)(n * C_ + c) * HW_) + q * 4096;

    float sm = 0.f, s2 = 0.f;
    #pragma unroll
    for (int i = 0; i < 16; i++) {             // 16 * 256 = 4096 float4
        float4 v = __ldg(p + i * 256 + threadIdx.x);
        sm += (v.x + v.y) + (v.z + v.w);
        s2 += v.x * v.x + v.y * v.y + v.z * v.z + v.w * v.w;
    }
    #pragma unroll
    for (int o = 16; o > 0; o >>= 1) {
        sm += __shfl_down_sync(0xFFFFFFFFu, sm, o);
        s2 += __shfl_down_sync(0xFFFFFFFFu, s2, o);
    }
    __shared__ float ss[8], ss2[8];
    __shared__ unsigned int s_old;
    const int wid = threadIdx.x >> 5, lid = threadIdx.x & 31;
    if (lid == 0) { ss[wid] = sm; ss2[wid] = s2; }
    __syncthreads();
    if (threadIdx.x == 0) {
        float ts = 0.f, ts2 = 0.f;
        #pragma unroll
        for (int i = 0; i < 8; i++) { ts += ss[i]; ts2 += ss2[i]; }
        g_part[n][c * 4 + q] = make_float2(ts, ts2);
        __threadfence();                       // release partial
        s_old = atomicAdd(&g_done[n], 1u);
    }
    __syncthreads();
    if (s_old == 511u) {                       // finisher: all partials visible
        __threadfence();
        if (threadIdx.x < C_) {
            const float2* pp = &g_part[n][threadIdx.x * 4];
            float ts  = (pp[0].x + pp[1].x) + (pp[2].x + pp[3].x);
            float ts2 = (pp[0].y + pp[1].y) + (pp[2].y + pp[3].y);
            const float inv_hw = 1.0f / (float)HW_;
            float mean = ts * inv_hw;
            float var  = ts2 * inv_hw - mean * mean;
            if (var < 0.f) var = 0.f;
            g_ms[n][threadIdx.x] = make_float2(mean, rsqrtf(var + EPS_));
        }
        __syncthreads();
        if (threadIdx.x == 0) {
            __threadfence();                   // release g_ms
            atomicExch(&g_ready[n], 1u);
        }
    }
    __syncthreads();
}

// ---------------------------------------------------------------------------
// Argmax item i in [0,512): 1024 consecutive pixels (thread = float4).
// ---------------------------------------------------------------------------
__device__ __forceinline__ void do_argmax_item(const float* __restrict__ seg, int i) {
    const int idx = i * THREADS + threadIdx.x;           // 0 .. 131071
    const int n   = idx >> 14;
    const int p4  = idx & 16383;
    const float4* __restrict__ s =
        reinterpret_cast<const float4*>(seg + (size_t)n * L_ * HW_) + p4;

    float4 best = __ldcs(s);
    int b0 = 0, b1 = 0, b2 = 0, b3 = 0;
    #pragma unroll
    for (int l = 1; l < L_; l++) {
        float4 v = __ldcs(s + (size_t)l * (HW_ / 4));
        if (v.x > best.x) { best.x = v.x; b0 = l; }
        if (v.y > best.y) { best.y = v.y; b1 = l; }
        if (v.z > best.z) { best.z = v.z; b2 = l; }
        if (v.w > best.w) { best.w = v.w; b3 = l; }
    }
    *reinterpret_cast<uchar4*>(g_cls + (size_t)n * HW_ + p4 * 4) =
        make_uchar4((unsigned char)b0, (unsigned char)b1,
                    (unsigned char)b2, (unsigned char)b3);
    __syncthreads();
    if (threadIdx.x == 0) {
        __threadfence();                       // release cls bytes
        atomicAdd(&g_argdone, 1u);
    }
    __syncthreads();
}

// ---------------------------------------------------------------------------
// Apply item a in [0,1024) for image n: cgroup = a&15 (8 ch), slab = a>>4
// (4 rows). Thread = float4 of pixels. Gates (usually open): g_ready[n],
// g_argdone==512. x: __ldcs (L2 hit from stats). out: __stcs streaming.
// ---------------------------------------------------------------------------
__device__ __forceinline__ void do_apply_item(
    const float* __restrict__ x, float* __restrict__ out,
    const float2* __restrict__ s_wb, int n, int a)
{
    // Gate: spin until image n's stats + the cls map are published.
    if (threadIdx.x == 0) {
        while (*(volatile unsigned int*)&g_ready[n] == 0u ||
               *(volatile unsigned int*)&g_argdone < 512u) { __nanosleep(64); }
        __threadfence();                       // acquire
    }
    __syncthreads();

    const int c0  = (a & 15) * CGRP;
    const int h0  = (a >> 4) << 2;
    const int tid = threadIdx.x;

    const int r    = tid >> 6;
    const int col4 = (tid & 63) << 2;
    const int pix  = (h0 + r) * W_ + col4;

    const uchar4 cl = *reinterpret_cast<const uchar4*>(g_cls + (size_t)n * HW_ + pix);
    const int i0 = cl.x * WB_STRIDE + c0, i1 = cl.y * WB_STRIDE + c0,
              i2 = cl.z * WB_STRIDE + c0, i3 = cl.w * WB_STRIDE + c0;

    const float* __restrict__ xn = x   + (size_t)(n * C_ + c0) * HW_ + pix;
    float*       __restrict__ on = out + (size_t)(n * C_ + c0) * HW_ + pix;

    float4 v[CGRP];
    #pragma unroll
    for (int c = 0; c < CGRP; c++)             // 8 outstanding 16B loads
        v[c] = __ldcs(reinterpret_cast<const float4*>(xn + (size_t)c * HW_));
    #pragma unroll
    for (int c = 0; c < CGRP; c++) {
        const float2 ms = __ldg(&g_ms[n][c0 + c]);   // uniform, L1/L2 hit
        const float2 w0 = s_wb[i0 + c];
        const float2 w1 = s_wb[i1 + c];
        const float2 w2 = s_wb[i2 + c];
        const float2 w3 = s_wb[i3 + c];
        float4 o;
        o.x = fmaf((v[c].x - ms.x) * ms.y, w0.x, w0.y);
        o.y = fmaf((v[c].y - ms.x) * ms.y, w1.x, w1.y);
        o.z = fmaf((v[c].z - ms.x) * ms.y, w2.x, w2.y);
        o.w = fmaf((v[c].w - ms.x) * ms.y, w3.x, w3.y);
        __stcs(reinterpret_cast<float4*>(on + (size_t)c * HW_), o);
    }
}

// ---------------------------------------------------------------------------
__global__ void __launch_bounds__(THREADS, 4) spade_fused_kernel(
    const float* __restrict__ x,
    const float* __restrict__ seg,
    const float* __restrict__ wgt,
    const float* __restrict__ bia,
    float* __restrict__ out)
{
    __shared__ float2 s_wb[L_ * WB_STRIDE];   // full merged (w,b) table
    __shared__ unsigned int s_t;

    // Stage the full (w,b) table once.
    for (int i = threadIdx.x; i < L_ * C_; i += THREADS) {
        int l = i >> 7, c = i & (C_ - 1);
        s_wb[l * WB_STRIDE + c] = make_float2(__ldg(wgt + i), __ldg(bia + i));
    }

    // ---- Drain the global ticket queue ----
    for (;;) {
        __syncthreads();
        if (threadIdx.x == 0) s_t = atomicAdd(&g_ticket, 1u);
        __syncthreads();
        const unsigned int t = s_t;
        if (t >= TOTAL_TKTS) break;

        if (t < REG0_END) {
            // Region 0: even -> argmax, odd -> stats(0)
            if (t & 1u) do_stats_item(x, 0, (int)(t >> 1));
            else        do_argmax_item(seg, (int)(t >> 1));
        } else if (t < REG8_BEGIN) {
            // Regions 1..7: per u: {stats(k,u), apply(k-1,2u), apply(k-1,2u+1)}
            const unsigned int q = t - REG0_END;
            const unsigned int k = q / REGK_SIZE + 1u;
            const unsigned int w = q - (k - 1u) * REGK_SIZE;
            const unsigned int u = w / 3u, pos = w - u * 3u;
            if (pos == 0u) do_stats_item(x, (int)k, (int)u);
            else           do_apply_item(x, out, s_wb, (int)(k - 1u),
                                         (int)(2u * u + pos - 1u));
        } else {
            // Region 8: apply(7)
            do_apply_item(x, out, s_wb, N_ - 1, (int)(t - REG8_BEGIN));
        }
    }

    // ---- Terminal barrier: master resets all pipeline state (replay-safe) ----
    __syncthreads();
    if (threadIdx.x == 0) {
        unsigned int snap = *(volatile unsigned int*)&g_gen;
        __threadfence();
        unsigned int c = atomicAdd(&g_count, 1u);
        if (c == GRID - 1) {
            atomicExch(&g_ticket, 0u);
            #pragma unroll
            for (int i = 0; i < N_; i++) {
                atomicExch(&g_done[i], 0u);
                atomicExch(&g_ready[i], 0u);
            }
            atomicExch(&g_argdone, 0u);
            atomicExch(&g_count, 0u);
            __threadfence();
            atomicAdd(&g_gen, 1u);
        } else {
            while (*(volatile unsigned int*)&g_gen == snap) { __nanosleep(64); }
        }
    }
    __syncthreads();
}

// ---------------------------------------------------------------------------
extern "C" void kernel_launch(void* const* d_in, const int* in_sizes, int n_in,
                              void* d_out, int out_size) {
    const float* x   = (const float*)d_in[0];
    const float* seg = (const float*)d_in[1];
    const float* wgt = (const float*)d_in[2];
    const float* bia = (const float*)d_in[3];
    float* out = (float*)d_out;

    spade_fused_kernel<<<GRID, THREADS>>>(x, seg, wgt, bia, out);
}